// round 15
// baseline (speedup 1.0000x reference)
#include <cuda_runtime.h>
#include <cstdint>

// Problem constants
#define EDIM   127
#define BN     2048                 // B*N
#define BNE    260096               // B*N*E

#define CT      512
#define NODES   8
#define GROUPS  256                 // BN / NODES

// Smem layout (floats). Total 28064 floats = 112256 B -> 2 blocks/SM.
#define OFF_W    0                  // 3 slots * 256 rows * 32 = 24576
#define OFF_B3   24576              // 3 * 256 = 768 (pre-scaled by 0.25)
#define OFF_H2   25344              // 8 nodes * 100 = 800
#define OFF_AX   26144              // 8 * 36 = 288
#define OFF_V4   26432              // 8 * 33 float4 = 1056 floats
#define OFF_VT   27488              // 16 * 36 = 576
#define SMF      28064
#define SMB      (SMF * 4)          // 112256

#define OUT1_BASE4 1040384          // (BNE*16)/4

// Per-(half, node) partial messages; every slot written exactly once per launch
__device__ float g_part[2 * BN * 64];

__device__ __forceinline__ float warp_sum(float v) {
    v += __shfl_xor_sync(0xffffffffu, v, 16);
    v += __shfl_xor_sync(0xffffffffu, v, 8);
    v += __shfl_xor_sync(0xffffffffu, v, 4);
    v += __shfl_xor_sync(0xffffffffu, v, 2);
    v += __shfl_xor_sync(0xffffffffu, v, 1);
    return v;
}

// packed fp32x2 FMA: d = a*b + d
__device__ __forceinline__ void ffma2(unsigned long long& d,
                                      unsigned long long a,
                                      unsigned long long b) {
    asm("fma.rn.f32x2 %0, %1, %2, %0;" : "+l"(d) : "l"(a), "l"(b));
}

// 8-float partial row dot from smem; bias (pre-scaled 0.25) folded into lo lane
__device__ __forceinline__ float dot8s(const float* wrow, float binit,
                                       const ulonglong2& h01, const ulonglong2& h23)
{
    const ulonglong2* wp = (const ulonglong2*)wrow;
    unsigned long long acA = (unsigned long long)__float_as_uint(binit);
    unsigned long long acB = 0ull;
    ulonglong2 wa = wp[0], wb = wp[1];
    ffma2(acA, wa.x, h01.x); ffma2(acB, wa.y, h01.y);
    ffma2(acA, wb.x, h23.x); ffma2(acB, wb.y, h23.y);
    asm("add.rn.f32x2 %0, %0, %1;" : "+l"(acA) : "l"(acB));
    return __uint_as_float((unsigned)acA) + __uint_as_float((unsigned)(acA >> 32));
}

// one radial-MLP column (layer1+LN+relu, layer2+LN+relu)
__device__ __forceinline__ void mlp_col(
    int m, float x, int k, float* vt, float* hout,
    const float* __restrict__ w1, const float* __restrict__ b1,
    const float* __restrict__ g1, const float* __restrict__ be1,
    const float* __restrict__ w2, const float* __restrict__ b2,
    const float* __restrict__ g2, const float* __restrict__ be2)
{
    float v = fmaf(x, w1[m * 32 + k], b1[m * 32 + k]);
    float mu = warp_sum(v) * (1.f / 32.f);
    float d = v - mu;
    float var = warp_sum(d * d) * (1.f / 32.f);
    v = fmaf(d * rsqrtf(var + 1e-5f), g1[m * 32 + k], be1[m * 32 + k]);
    v = fmaxf(v, 0.f);
    vt[k] = v;
    __syncwarp();
    const float4* w2r4 = (const float4*)(w2 + (m * 32 + k) * 32);
    const float4* vt4  = (const float4*)vt;
    float a0 = b2[m * 32 + k], a1 = 0.f;
    #pragma unroll
    for (int q = 0; q < 8; q += 2) {
        float4 wv0 = __ldg(&w2r4[q]);     float4 vv0 = vt4[q];
        float4 wv1 = __ldg(&w2r4[q + 1]); float4 vv1 = vt4[q + 1];
        a0 = fmaf(wv0.x, vv0.x, a0); a0 = fmaf(wv0.y, vv0.y, a0);
        a0 = fmaf(wv0.z, vv0.z, a0); a0 = fmaf(wv0.w, vv0.w, a0);
        a1 = fmaf(wv1.x, vv1.x, a1); a1 = fmaf(wv1.y, vv1.y, a1);
        a1 = fmaf(wv1.z, vv1.z, a1); a1 = fmaf(wv1.w, vv1.w, a1);
    }
    float acc = a0 + a1;
    float mu2 = warp_sum(acc) * (1.f / 32.f);
    float d2 = acc - mu2;
    float var2 = warp_sum(d2 * d2) * (1.f / 32.f);
    acc = fmaf(d2 * rsqrtf(var2 + 1e-5f), g2[m * 32 + k], be2[m * 32 + k]);
    acc = fmaxf(acc, 0.f);
    *hout = acc;
    __syncwarp();
}

__device__ __forceinline__ float4 v11_entry(const float* __restrict__ src1,
                                            const float* __restrict__ b11g,
                                            int eb, int node0, int X)
{
    int jj = X / 3, f = X - jj * 3;
    float sa = src1[eb * 48 + jj * 3 + 0];
    float sb = src1[eb * 48 + jj * 3 + 1];
    float sc = src1[eb * 48 + jj * 3 + 2];
    float v0 = b11g[node0 * 27 + 0 + f] * sa + b11g[node0 * 27 + 3 + f] * sb
             + b11g[node0 * 27 + 6 + f] * sc;
    float v1 = b11g[node0 * 27 + 9 + f] * sa + b11g[node0 * 27 + 12 + f] * sb
             + b11g[node0 * 27 + 15 + f] * sc;
    float v2 = b11g[node0 * 27 + 18 + f] * sa + b11g[node0 * 27 + 21 + f] * sb
             + b11g[node0 * 27 + 24 + f] * sc;
    return make_float4(v0, v1, v2, 0.f);
}

extern "C" __global__ void __launch_bounds__(CT, 2)
compute_kernel(const float* __restrict__ r,
               const float* __restrict__ src0,
               const float* __restrict__ src1,
               const float* __restrict__ b00g,
               const float* __restrict__ b01g,
               const float* __restrict__ b10g,
               const float* __restrict__ b11g,
               const float* __restrict__ w1,
               const float* __restrict__ b1,
               const float* __restrict__ g1,
               const float* __restrict__ be1,
               const float* __restrict__ w2,
               const float* __restrict__ b2,
               const float* __restrict__ g2,
               const float* __restrict__ be2,
               const float* __restrict__ w300, const float* __restrict__ b300,
               const float* __restrict__ w301, const float* __restrict__ b301,
               const float* __restrict__ w310, const float* __restrict__ b310,
               const float* __restrict__ w311, const float* __restrict__ b311)
{
    extern __shared__ float sm[];
    float*  Wsm  = sm + OFF_W;
    float4* Wsm4 = (float4*)Wsm;
    float*  b3s  = sm + OFF_B3;
    float*  h2s  = sm + OFF_H2;    // [node*100 + hslot*32 + k]
    float*  axs  = sm + OFF_AX;    // [node*36]: A: c00|s0|b01  B: ws1
    float4* v4s  = (float4*)(sm + OFF_V4);  // [node*33 + X]
    float*  vts  = sm + OFF_VT;    // [warp*36]

    const int t    = threadIdx.x;
    const int lane = t & 31;
    const int w    = t >> 5;            // 0..15
    const int blk  = blockIdx.x;
    const int hB   = blockIdx.y;        // 0 = half A, 1 = half B

    // ---- stage 3 weight slots (float4) ----
    for (int d4 = t; d4 < 6144; d4 += CT) {
        int slot = d4 >> 11, rem = d4 & 2047;
        int rowq = rem >> 3, k4 = rem & 7;
        const float4* src; int srow;
        if (!hB) {
            if (slot == 0)      { src = (const float4*)w300; srow = rowq; }
            else if (slot == 1) { src = (const float4*)w301; srow = rowq; }
            else { src = (const float4*)w311; srow = (rowq >> 4) * 48 + (rowq & 15); }
        } else {
            if (slot == 0)      { src = (const float4*)w310; srow = rowq; }
            else {
                src = (const float4*)w311;
                srow = (rowq >> 4) * 48 + (slot == 1 ? 16 : 32) + (rowq & 15);
            }
        }
        Wsm4[slot * 2048 + rowq * 8 + k4] = src[srow * 8 + k4];
    }
    // ---- stage biases, pre-scaled by 0.25 (4-way k split sums to 1.0) ----
    for (int idx = t; idx < 768; idx += CT) {
        int slot = idx >> 8, rowq = idx & 255;
        const float* bs; int srow;
        if (!hB) {
            if (slot == 0)      { bs = b300; srow = rowq; }
            else if (slot == 1) { bs = b301; srow = rowq; }
            else { bs = b311; srow = (rowq >> 4) * 48 + (rowq & 15); }
        } else {
            if (slot == 0)      { bs = b310; srow = rowq; }
            else { bs = b311; srow = (rowq >> 4) * 48 + (slot == 1 ? 16 : 32) + (rowq & 15); }
        }
        b3s[idx] = 0.25f * bs[srow];
    }

    // ---- prologue MLPs ----
    // half A: warps 0-7  -> node w,   m0 (hslot0) and m1 (hslot1)
    //         warps 8-15 -> node w-8, m3 (hslot2)
    // half B: warps 0-7  -> node w,   m2 (hslot0)
    //         warps 8-15 -> node w-8, m3 (hslot1)
    const int pnode = w & 7;
    const int node0 = blk * NODES + pnode;
    const int eb    = node0 * EDIM;
    const float x   = r[eb];
    const int k     = lane;
    float* vt = vts + w * 36;

    if (!hB) {
        if (w < 8) {
            mlp_col(0, x, k, vt, &h2s[pnode * 100 + 0 * 32 + k],
                    w1, b1, g1, be1, w2, b2, g2, be2);
            mlp_col(1, x, k, vt, &h2s[pnode * 100 + 1 * 32 + k],
                    w1, b1, g1, be1, w2, b2, g2, be2);
        } else {
            mlp_col(3, x, k, vt, &h2s[pnode * 100 + 2 * 32 + k],
                    w1, b1, g1, be1, w2, b2, g2, be2);
        }
    } else {
        const int m  = (w < 8) ? 2 : 3;
        const int hs = (w < 8) ? 0 : 1;
        mlp_col(m, x, k, vt, &h2s[pnode * 100 + hs * 32 + k],
                w1, b1, g1, be1, w2, b2, g2, be2);
    }

    // ---- per-node aux ----
    if (lane < 16) {
        const int j = lane;
        if (w < 8) {
            if (!hB) {
                float s0v = src0[eb * 16 + j];
                axs[pnode * 36 + j]      = b00g[node0] * s0v;     // c00
                axs[pnode * 36 + 16 + j] = s0v;                   // s0
                if (j < 3) axs[pnode * 36 + 32 + j] = b01g[node0 * 3 + j];
            } else {
                float s1a = src1[eb * 48 + j * 3 + 0];
                float s1b = src1[eb * 48 + j * 3 + 1];
                float s1c = src1[eb * 48 + j * 3 + 2];
                axs[pnode * 36 + j] = b10g[node0 * 3 + 0] * s1a   // ws1
                                    + b10g[node0 * 3 + 1] * s1b
                                    + b10g[node0 * 3 + 2] * s1c;
            }
        } else {
            if (!hB) {
                v4s[pnode * 33 + j] = v11_entry(src1, b11g, eb, node0, j);          // cc0
            } else {
                v4s[pnode * 33 + j]      = v11_entry(src1, b11g, eb, node0, 16 + j); // cc1
                v4s[pnode * 33 + 16 + j] = v11_entry(src1, b11g, eb, node0, 32 + j); // cc2
            }
        }
    }
    __syncthreads();

    // ---- main loop: warp = out-channel i; lane = node*4 + kq ----
    const int i    = w;
    const int node = lane >> 2;
    const int kq   = lane & 3;
    const int koff = kq * 8;

    const float* axn   = axs + node * 36;
    const float4* v4n  = v4s + node * 33;
    const float* hbase = h2s + node * 100;
    const float b01r0 = hB ? 0.f : axn[32];
    const float b01r1 = hB ? 0.f : axn[33];
    const float b01r2 = hB ? 0.f : axn[34];

    float z0 = 0.f, y0 = 0.f, y1 = 0.f, y2 = 0.f;
    ulonglong2 h01, h23;

#define LOAD_HS(hs) { const ulonglong2* hp = \
        (const ulonglong2*)(hbase + (hs) * 32 + koff); \
    h01 = hp[0]; h23 = hp[1]; }

#define V4_SLOT(slot, vvp) { \
    const float* wb = Wsm + (slot) * 8192 + i * 512 + koff; \
    const float* bb = b3s + (slot) * 256 + i * 16; \
    _Pragma("unroll") \
    for (int g4 = 0; g4 < 4; g4++) { \
        float4 bq = *(const float4*)(bb + g4 * 4); \
        float sA = dot8s(wb + (g4 * 4 + 0) * 32, bq.x, h01, h23); \
        float sB = dot8s(wb + (g4 * 4 + 1) * 32, bq.y, h01, h23); \
        float sC = dot8s(wb + (g4 * 4 + 2) * 32, bq.z, h01, h23); \
        float sD = dot8s(wb + (g4 * 4 + 3) * 32, bq.w, h01, h23); \
        float4 vA = (vvp)[g4 * 4 + 0], vB = (vvp)[g4 * 4 + 1]; \
        float4 vC = (vvp)[g4 * 4 + 2], vD = (vvp)[g4 * 4 + 3]; \
        y0 = fmaf(sA, vA.x, y0); y1 = fmaf(sA, vA.y, y1); y2 = fmaf(sA, vA.z, y2); \
        y0 = fmaf(sB, vB.x, y0); y1 = fmaf(sB, vB.y, y1); y2 = fmaf(sB, vB.z, y2); \
        y0 = fmaf(sC, vC.x, y0); y1 = fmaf(sC, vC.y, y1); y2 = fmaf(sC, vC.z, y2); \
        y0 = fmaf(sD, vD.x, y0); y1 = fmaf(sD, vD.y, y1); y2 = fmaf(sD, vD.z, y2); \
    } }

    // slot 0 (A: ch00 via c00, B: ch10 via ws1) -> z0
    LOAD_HS(0);
    {
        const float* wb = Wsm + i * 512 + koff;
        const float* bb = b3s + i * 16;
        #pragma unroll
        for (int g4 = 0; g4 < 4; g4++) {
            float4 bq = *(const float4*)(bb + g4 * 4);
            float4 aq = *(const float4*)(axn + g4 * 4);
            float sA = dot8s(wb + (g4 * 4 + 0) * 32, bq.x, h01, h23);
            float sB = dot8s(wb + (g4 * 4 + 1) * 32, bq.y, h01, h23);
            float sC = dot8s(wb + (g4 * 4 + 2) * 32, bq.z, h01, h23);
            float sD = dot8s(wb + (g4 * 4 + 3) * 32, bq.w, h01, h23);
            z0 = fmaf(sA, aq.x, z0); z0 = fmaf(sB, aq.y, z0);
            z0 = fmaf(sC, aq.z, z0); z0 = fmaf(sD, aq.w, z0);
        }
    }

    if (!hB) {
        // slot 1 (ch01): tts = sum s*s0 -> y += tts * b01
        LOAD_HS(1);
        float tts = 0.f;
        {
            const float* wb = Wsm + 8192 + i * 512 + koff;
            const float* bb = b3s + 256 + i * 16;
            #pragma unroll
            for (int g4 = 0; g4 < 4; g4++) {
                float4 bq = *(const float4*)(bb + g4 * 4);
                float4 aq = *(const float4*)(axn + 16 + g4 * 4);
                float sA = dot8s(wb + (g4 * 4 + 0) * 32, bq.x, h01, h23);
                float sB = dot8s(wb + (g4 * 4 + 1) * 32, bq.y, h01, h23);
                float sC = dot8s(wb + (g4 * 4 + 2) * 32, bq.z, h01, h23);
                float sD = dot8s(wb + (g4 * 4 + 3) * 32, bq.w, h01, h23);
                tts = fmaf(sA, aq.x, tts); tts = fmaf(sB, aq.y, tts);
                tts = fmaf(sC, aq.z, tts); tts = fmaf(sD, aq.w, tts);
            }
        }
        y0 = fmaf(tts, b01r0, y0);
        y1 = fmaf(tts, b01r1, y1);
        y2 = fmaf(tts, b01r2, y2);
        // slot 2 (ch11 cc0): v4-type, h slot2
        LOAD_HS(2);
        V4_SLOT(2, v4n);
    } else {
        // slots 1,2 (ch11 cc1, cc2): v4-type, both use h slot1
        LOAD_HS(1);
        V4_SLOT(1, v4n);
        V4_SLOT(2, (v4n + 16));
    }

    // reduce over kq and write partial messages
    z0 += __shfl_xor_sync(0xffffffffu, z0, 1);
    y0 += __shfl_xor_sync(0xffffffffu, y0, 1);
    y1 += __shfl_xor_sync(0xffffffffu, y1, 1);
    y2 += __shfl_xor_sync(0xffffffffu, y2, 1);
    z0 += __shfl_xor_sync(0xffffffffu, z0, 2);
    y0 += __shfl_xor_sync(0xffffffffu, y0, 2);
    y1 += __shfl_xor_sync(0xffffffffu, y1, 2);
    y2 += __shfl_xor_sync(0xffffffffu, y2, 2);

    if (kq == 0) {
        float* dst = g_part + (size_t)hB * (BN * 64)
                   + (size_t)(blk * NODES + node) * 64;
        dst[i] = z0;
        dst[16 + i * 3 + 0] = y0;
        dst[16 + i * 3 + 1] = y1;
        dst[16 + i * 3 + 2] = y2;
    }
}

// ---- broadcast: sum 2 halves per node, fan out to 127 edges (2 nodes/block) ----
extern "C" __global__ void __launch_bounds__(512)
broadcast_kernel(float4* __restrict__ out)
{
    const int nn = threadIdx.x >> 8;
    const int tt = threadIdx.x & 255;
    const int bn = blockIdx.x * 2 + nn;

    const float4* a = (const float4*)(g_part + (size_t)bn * 64);
    const float4* b = (const float4*)(g_part + (size_t)(BN * 64) + (size_t)bn * 64);

    // out0 value (period 4)
    const int i03 = tt & 3;
    float4 xa = __ldg(&a[i03]), xb = __ldg(&b[i03]);
    float4 v0 = make_float4(xa.x + xb.x, xa.y + xb.y, xa.z + xb.z, xa.w + xb.w);

    // out1 values (period 12; stride 256 == +4 mod 12 -> 3 rotating values)
    int s12 = tt % 12;
    int sb = s12 + 4; if (sb >= 12) sb -= 12;
    int sc = s12 + 8; if (sc >= 12) sc -= 12;
    float4 pa = __ldg(&a[4 + s12]), qa = __ldg(&b[4 + s12]);
    float4 pb = __ldg(&a[4 + sb]),  qb = __ldg(&b[4 + sb]);
    float4 pc = __ldg(&a[4 + sc]),  qc = __ldg(&b[4 + sc]);
    float4 va = make_float4(pa.x + qa.x, pa.y + qa.y, pa.z + qa.z, pa.w + qa.w);
    float4 vb = make_float4(pb.x + qb.x, pb.y + qb.y, pb.z + qb.z, pb.w + qb.w);
    float4 vc = make_float4(pc.x + qc.x, pc.y + qc.y, pc.z + qc.z, pc.w + qc.w);

    float4* o0 = out + (size_t)bn * 508;
    o0[tt] = v0;
    if (tt < 252) o0[tt + 256] = v0;

    float4* o1 = out + OUT1_BASE4 + (size_t)bn * 1524;
    o1[tt]        = va;
    o1[tt + 256]  = vb;
    o1[tt + 512]  = vc;
    o1[tt + 768]  = va;
    o1[tt + 1024] = vb;
    if (tt < 244) o1[tt + 1280] = vc;
}

extern "C" void kernel_launch(void* const* d_in, const int* in_sizes, int n_in,
                              void* d_out, int out_size)
{
    const float* r    = (const float*)d_in[0];
    const float* src0 = (const float*)d_in[1];
    const float* src1 = (const float*)d_in[2];
    const float* b00  = (const float*)d_in[3];
    const float* b01  = (const float*)d_in[4];
    const float* b10  = (const float*)d_in[5];
    const float* b11  = (const float*)d_in[6];
    const float* w1   = (const float*)d_in[7];
    const float* b1   = (const float*)d_in[8];
    const float* g1   = (const float*)d_in[9];
    const float* be1  = (const float*)d_in[10];
    const float* w2   = (const float*)d_in[11];
    const float* b2   = (const float*)d_in[12];
    const float* g2   = (const float*)d_in[13];
    const float* be2  = (const float*)d_in[14];
    const float* w300 = (const float*)d_in[15];
    const float* b300 = (const float*)d_in[16];
    const float* w301 = (const float*)d_in[17];
    const float* b301 = (const float*)d_in[18];
    const float* w310 = (const float*)d_in[19];
    const float* b310 = (const float*)d_in[20];
    const float* w311 = (const float*)d_in[21];
    const float* b311 = (const float*)d_in[22];

    cudaFuncSetAttribute(compute_kernel,
                         cudaFuncAttributeMaxDynamicSharedMemorySize, SMB);

    compute_kernel<<<dim3(GROUPS, 2), CT, SMB>>>(
        r, src0, src1, b00, b01, b10, b11,
        w1, b1, g1, be1, w2, b2, g2, be2,
        w300, b300, w301, b301, w310, b310, w311, b311);

    broadcast_kernel<<<BN / 2, 512>>>((float4*)d_out);
}

// round 17
// speedup vs baseline: 1.3928x; 1.3928x over previous
#include <cuda_runtime.h>
#include <cstdint>

// Problem constants
#define EDIM   127
#define BN     2048                 // B*N
#define BNE    260096               // B*N*E

#define CT      1024
#define NODES   16
#define GROUPS  128                 // BN / NODES

// Smem layout (floats). Total 57936 floats = 231744 B (<= 232448 opt-in).
#define OFF_W    0                  // 6 slots * 256 rows * 32 = 49152
#define OFF_B3   49152              // 1536
#define OFF_H2   50688              // 16 * 132 = 2112 (aliased by msgA after sync)
#define OFF_AX   52800              // 16 * 53 = 848
#define OFF_V11  53648              // 16 * 49 float4 = 3136 floats (aliased by msgB)
#define OFF_VT   56784              // 32 * 36 = 1152
#define SMF      57936
#define SMB      (SMF * 4)          // 231744

#define H2PAD  132
#define AXPAD  53
#define V11PAD 49
#define VTPAD  36

#define OUT1_BASE4 1040384          // (BNE*16)/4

__device__ __forceinline__ float warp_sum(float v) {
    v += __shfl_xor_sync(0xffffffffu, v, 16);
    v += __shfl_xor_sync(0xffffffffu, v, 8);
    v += __shfl_xor_sync(0xffffffffu, v, 4);
    v += __shfl_xor_sync(0xffffffffu, v, 2);
    v += __shfl_xor_sync(0xffffffffu, v, 1);
    return v;
}

// packed fp32x2 FMA: d = a*b + d
__device__ __forceinline__ void ffma2(unsigned long long& d,
                                      unsigned long long a,
                                      unsigned long long b) {
    asm("fma.rn.f32x2 %0, %1, %2, %0;" : "+l"(d) : "l"(a), "l"(b));
}

// 16-float half-row dot from smem (bias pre-halved; both khalves add it)
__device__ __forceinline__ float dot_row(const float* wrow, float binit,
                                         const ulonglong2& hp0, const ulonglong2& hp1,
                                         const ulonglong2& hp2, const ulonglong2& hp3)
{
    const ulonglong2* wp = (const ulonglong2*)wrow;
    unsigned long long acA = (unsigned long long)__float_as_uint(binit);
    unsigned long long acB = 0ull;
    ulonglong2 wa = wp[0], wb = wp[1];
    ffma2(acA, wa.x, hp0.x); ffma2(acB, wa.y, hp0.y);
    ffma2(acA, wb.x, hp1.x); ffma2(acB, wb.y, hp1.y);
    wa = wp[2]; wb = wp[3];
    ffma2(acA, wa.x, hp2.x); ffma2(acB, wa.y, hp2.y);
    ffma2(acA, wb.x, hp3.x); ffma2(acB, wb.y, hp3.y);
    asm("add.rn.f32x2 %0, %0, %1;" : "+l"(acA) : "l"(acB));
    return __uint_as_float((unsigned)acA) + __uint_as_float((unsigned)(acA >> 32));
}

// one radial-MLP column (layer1+LN+relu, layer2+LN+relu); v staged in smem
__device__ __forceinline__ void mlp_col(
    int m, float x, int k, float* vt, float* hout,
    const float* __restrict__ w1, const float* __restrict__ b1,
    const float* __restrict__ g1, const float* __restrict__ be1,
    const float* __restrict__ w2, const float* __restrict__ b2,
    const float* __restrict__ g2, const float* __restrict__ be2)
{
    float v = fmaf(x, w1[m * 32 + k], b1[m * 32 + k]);
    float mu = warp_sum(v) * (1.f / 32.f);
    float d = v - mu;
    float var = warp_sum(d * d) * (1.f / 32.f);
    v = fmaf(d * rsqrtf(var + 1e-5f), g1[m * 32 + k], be1[m * 32 + k]);
    v = fmaxf(v, 0.f);
    vt[k] = v;
    __syncwarp();
    const float4* w2r4 = (const float4*)(w2 + (m * 32 + k) * 32);
    const float4* vt4  = (const float4*)vt;
    float a0 = b2[m * 32 + k], a1 = 0.f;
    #pragma unroll
    for (int q = 0; q < 8; q += 2) {
        float4 wv0 = __ldg(&w2r4[q]);     float4 vv0 = vt4[q];
        float4 wv1 = __ldg(&w2r4[q + 1]); float4 vv1 = vt4[q + 1];
        a0 = fmaf(wv0.x, vv0.x, a0); a0 = fmaf(wv0.y, vv0.y, a0);
        a0 = fmaf(wv0.z, vv0.z, a0); a0 = fmaf(wv0.w, vv0.w, a0);
        a1 = fmaf(wv1.x, vv1.x, a1); a1 = fmaf(wv1.y, vv1.y, a1);
        a1 = fmaf(wv1.z, vv1.z, a1); a1 = fmaf(wv1.w, vv1.w, a1);
    }
    float acc = a0 + a1;
    float mu2 = warp_sum(acc) * (1.f / 32.f);
    float d2 = acc - mu2;
    float var2 = warp_sum(d2 * d2) * (1.f / 32.f);
    acc = fmaf(d2 * rsqrtf(var2 + 1e-5f), g2[m * 32 + k], be2[m * 32 + k]);
    acc = fmaxf(acc, 0.f);
    *hout = acc;
    __syncwarp();
}

__device__ __forceinline__ float4 v11_entry(const float* __restrict__ src1,
                                            const float* __restrict__ b11g,
                                            int eb, int node0, int X)
{
    int jj = X / 3, f = X - jj * 3;
    float sa = src1[eb * 48 + jj * 3 + 0];
    float sb = src1[eb * 48 + jj * 3 + 1];
    float sc = src1[eb * 48 + jj * 3 + 2];
    float v0 = b11g[node0 * 27 + 0 + f] * sa + b11g[node0 * 27 + 3 + f] * sb
             + b11g[node0 * 27 + 6 + f] * sc;
    float v1 = b11g[node0 * 27 + 9 + f] * sa + b11g[node0 * 27 + 12 + f] * sb
             + b11g[node0 * 27 + 15 + f] * sc;
    float v2 = b11g[node0 * 27 + 18 + f] * sa + b11g[node0 * 27 + 21 + f] * sb
             + b11g[node0 * 27 + 24 + f] * sc;
    return make_float4(v0, v1, v2, 0.f);
}

extern "C" __global__ void __launch_bounds__(CT, 1)
fused_kernel(const float* __restrict__ r,
             const float* __restrict__ src0,
             const float* __restrict__ src1,
             const float* __restrict__ b00g,
             const float* __restrict__ b01g,
             const float* __restrict__ b10g,
             const float* __restrict__ b11g,
             const float* __restrict__ w1,
             const float* __restrict__ b1,
             const float* __restrict__ g1,
             const float* __restrict__ be1,
             const float* __restrict__ w2,
             const float* __restrict__ b2,
             const float* __restrict__ g2,
             const float* __restrict__ be2,
             const float* __restrict__ w300, const float* __restrict__ b300,
             const float* __restrict__ w301, const float* __restrict__ b301,
             const float* __restrict__ w310, const float* __restrict__ b310,
             const float* __restrict__ w311, const float* __restrict__ b311,
             float4* __restrict__ out)
{
    extern __shared__ float sm[];
    float*  Wsm  = sm + OFF_W;
    float4* Wsm4 = (float4*)Wsm;
    float*  b3s  = sm + OFF_B3;
    float*  h2s  = sm + OFF_H2;
    float*  axs  = sm + OFF_AX;
    float4* v4s  = (float4*)(sm + OFF_V11);
    float*  vts  = sm + OFF_VT;

    const int t    = threadIdx.x;
    const int lane = t & 31;
    const int w    = t >> 5;           // 0..31
    const int blk  = blockIdx.x;

    // ---- stage 6 weight slots ----
    for (int d4 = t; d4 < 12288; d4 += CT) {
        int slot = d4 >> 11, rem = d4 & 2047;
        int rowq = rem >> 3, k4 = rem & 7;
        const float4* src; int srow;
        if (slot == 0)      { src = (const float4*)w300; srow = rowq; }
        else if (slot == 1) { src = (const float4*)w301; srow = rowq; }
        else if (slot == 2) { src = (const float4*)w310; srow = rowq; }
        else {
            src = (const float4*)w311;
            srow = (rowq >> 4) * 48 + (slot - 3) * 16 + (rowq & 15);
        }
        Wsm4[slot * 2048 + rowq * 8 + k4] = src[srow * 8 + k4];
    }
    for (int idx = t; idx < 1536; idx += CT) {
        int slot = idx >> 8, rowq = idx & 255;
        const float* bs; int srow;
        if (slot == 0)      { bs = b300; srow = rowq; }
        else if (slot == 1) { bs = b301; srow = rowq; }
        else if (slot == 2) { bs = b310; srow = rowq; }
        else { bs = b311; srow = (rowq >> 4) * 48 + (slot - 3) * 16 + (rowq & 15); }
        b3s[idx] = bs[srow];
    }

    // ---- prologue: warp w -> node (w&15), m-pair (w>>4) ----
    const int pnode = w & 15;
    const int mpair = w >> 4;
    const int node0 = blk * NODES + pnode;
    const int eb    = node0 * EDIM;
    const float x   = r[eb];
    const int k     = lane;
    float* vt = vts + w * VTPAD;

    {
        const int m0 = mpair * 2;
        mlp_col(m0, x, k, vt, &h2s[pnode * H2PAD + m0 * 32 + k],
                w1, b1, g1, be1, w2, b2, g2, be2);
        mlp_col(m0 + 1, x, k, vt, &h2s[pnode * H2PAD + (m0 + 1) * 32 + k],
                w1, b1, g1, be1, w2, b2, g2, be2);
    }

    // ---- per-node aux: warps 0-15 -> axs; warps 16-31 -> v11 ----
    if (lane < 16) {
        const int j = lane;
        if (mpair == 0) {
            float s0v = src0[eb * 16 + j];
            float s1a = src1[eb * 48 + j * 3 + 0];
            float s1b = src1[eb * 48 + j * 3 + 1];
            float s1c = src1[eb * 48 + j * 3 + 2];
            axs[pnode * AXPAD + j]      = b00g[node0] * s0v;          // c00
            axs[pnode * AXPAD + 16 + j] = s0v;                        // s0
            axs[pnode * AXPAD + 32 + j] = b10g[node0 * 3 + 0] * s1a   // ws1
                                        + b10g[node0 * 3 + 1] * s1b
                                        + b10g[node0 * 3 + 2] * s1c;
            if (j < 3) axs[pnode * AXPAD + 48 + j] = b01g[node0 * 3 + j];
        } else {
            v4s[pnode * V11PAD + j]      = v11_entry(src1, b11g, eb, node0, j);
            v4s[pnode * V11PAD + 16 + j] = v11_entry(src1, b11g, eb, node0, 16 + j);
            v4s[pnode * V11PAD + 32 + j] = v11_entry(src1, b11g, eb, node0, 32 + j);
        }
    }
    __syncthreads();

    // ---- main loop: warp = (group, out-channel i); lane = (node, khalf) ----
    const int grp   = w >> 4;          // 0: slots 0-2, 1: slots 3-5
    const int i     = w & 15;
    const int node  = lane >> 1;
    const int khalf = lane & 1;

    const float* axn  = axs + node * AXPAD;
    const float4* v4n = v4s + node * V11PAD;
    const ulonglong2* hbase = (const ulonglong2*)(h2s + node * H2PAD + khalf * 16);

    float z0 = 0.f, y0 = 0.f, y1 = 0.f, y2 = 0.f;
    ulonglong2 hp0, hp1, hp2, hp3;

#define LOAD_HP(m) { const ulonglong2* hp = hbase + (m) * 8; \
    hp0 = hp[0]; hp1 = hp[1]; hp2 = hp[2]; hp3 = hp[3]; }

    if (grp == 0) {
        float tts = 0.f;
        // slot0 (ch00, m0) -> z0 via c00
        LOAD_HP(0);
        {
            const float* wb = Wsm + (0 * 256 + i * 16) * 32 + khalf * 16;
            const float* bb = b3s + 0 * 256 + i * 16;
            #pragma unroll 4
            for (int gq = 0; gq < 16; gq++) {
                float s = dot_row(wb + gq * 32, 0.5f * bb[gq], hp0, hp1, hp2, hp3);
                z0 = fmaf(s, axn[gq], z0);
            }
        }
        // slot1 (ch01, m1) -> tts via s0
        LOAD_HP(1);
        {
            const float* wb = Wsm + (1 * 256 + i * 16) * 32 + khalf * 16;
            const float* bb = b3s + 1 * 256 + i * 16;
            #pragma unroll 4
            for (int gq = 0; gq < 16; gq++) {
                float s = dot_row(wb + gq * 32, 0.5f * bb[gq], hp0, hp1, hp2, hp3);
                tts = fmaf(s, axn[16 + gq], tts);
            }
        }
        // slot2 (ch10, m2) -> z0 via ws1
        LOAD_HP(2);
        {
            const float* wb = Wsm + (2 * 256 + i * 16) * 32 + khalf * 16;
            const float* bb = b3s + 2 * 256 + i * 16;
            #pragma unroll 4
            for (int gq = 0; gq < 16; gq++) {
                float s = dot_row(wb + gq * 32, 0.5f * bb[gq], hp0, hp1, hp2, hp3);
                z0 = fmaf(s, axn[32 + gq], z0);
            }
        }
        y0 = tts * axn[48];
        y1 = tts * axn[49];
        y2 = tts * axn[50];
    } else {
        // slots 3-5 (ch11 cc0..2, m3) -> y via v11
        LOAD_HP(3);
        #pragma unroll 1
        for (int cc = 0; cc < 3; cc++) {
            const float* wb = Wsm + ((3 + cc) * 256 + i * 16) * 32 + khalf * 16;
            const float* bb = b3s + (3 + cc) * 256 + i * 16;
            const float4* vv = v4n + cc * 16;
            #pragma unroll 4
            for (int gq = 0; gq < 16; gq++) {
                float s = dot_row(wb + gq * 32, 0.5f * bb[gq], hp0, hp1, hp2, hp3);
                float4 vg = vv[gq];
                y0 = fmaf(s, vg.x, y0);
                y1 = fmaf(s, vg.y, y1);
                y2 = fmaf(s, vg.z, y2);
            }
        }
    }

    // combine k-halves
    z0 += __shfl_xor_sync(0xffffffffu, z0, 1);
    y0 += __shfl_xor_sync(0xffffffffu, y0, 1);
    y1 += __shfl_xor_sync(0xffffffffu, y1, 1);
    y2 += __shfl_xor_sync(0xffffffffu, y2, 1);

    // ---- write partial messages (msgA aliases h2s, msgB aliases v11) ----
    __syncthreads();                 // all h2s / v4s reads complete
    float* msgA = h2s;               // [node][64] = msg0[16] | msg1[48]
    float* msgB = (float*)v4s;       // [node][48]
    if (khalf == 0) {
        if (grp == 0) {
            msgA[node * 64 + i] = z0;
            msgA[node * 64 + 16 + i * 3 + 0] = y0;
            msgA[node * 64 + 16 + i * 3 + 1] = y1;
            msgA[node * 64 + 16 + i * 3 + 2] = y2;
        } else {
            msgB[node * 48 + i * 3 + 0] = y0;
            msgB[node * 48 + i * 3 + 1] = y1;
            msgB[node * 48 + i * 3 + 2] = y2;
        }
    }
    __syncthreads();

    // merge group-1 partials into msgA (float4-wise)
    if (t < 192) {                   // 16 nodes * 12 float4
        int nn = t / 12, q = t - nn * 12;
        float4* a = (float4*)msgA + nn * 16 + 4 + q;
        float4  b = ((float4*)msgB)[nn * 12 + q];
        float4  v = *a;
        *a = make_float4(v.x + b.x, v.y + b.y, v.z + b.z, v.w + b.w);
    }
    __syncthreads();

    // ---- fused broadcast: 16 nodes -> 127 edges each ----
    const float4* mq = (const float4*)msgA;
    const int bn0 = blk * NODES;
    int s12 = t % 12;
    int sb = s12 + 4; if (sb >= 12) sb -= 12;   // (t+1024) % 12

    #pragma unroll 1
    for (int nn = 0; nn < NODES; nn++) {
        const float4* mrow = mq + nn * 16;      // [0..3]=msg0, [4..15]=msg1
        // out0: 508 float4, period 4
        float4* o0 = out + (size_t)(bn0 + nn) * 508;
        if (t < 508) o0[t] = mrow[t & 3];
        // out1: 1524 float4 = 1024 + 500, period 12
        float4* o1 = out + OUT1_BASE4 + (size_t)(bn0 + nn) * 1524;
        o1[t] = mrow[4 + s12];
        if (t < 500) o1[t + 1024] = mrow[4 + sb];
    }
}

extern "C" void kernel_launch(void* const* d_in, const int* in_sizes, int n_in,
                              void* d_out, int out_size)
{
    const float* r    = (const float*)d_in[0];
    const float* src0 = (const float*)d_in[1];
    const float* src1 = (const float*)d_in[2];
    const float* b00  = (const float*)d_in[3];
    const float* b01  = (const float*)d_in[4];
    const float* b10  = (const float*)d_in[5];
    const float* b11  = (const float*)d_in[6];
    const float* w1   = (const float*)d_in[7];
    const float* b1   = (const float*)d_in[8];
    const float* g1   = (const float*)d_in[9];
    const float* be1  = (const float*)d_in[10];
    const float* w2   = (const float*)d_in[11];
    const float* b2   = (const float*)d_in[12];
    const float* g2   = (const float*)d_in[13];
    const float* be2  = (const float*)d_in[14];
    const float* w300 = (const float*)d_in[15];
    const float* b300 = (const float*)d_in[16];
    const float* w301 = (const float*)d_in[17];
    const float* b301 = (const float*)d_in[18];
    const float* w310 = (const float*)d_in[19];
    const float* b310 = (const float*)d_in[20];
    const float* w311 = (const float*)d_in[21];
    const float* b311 = (const float*)d_in[22];

    cudaFuncSetAttribute(fused_kernel,
                         cudaFuncAttributeMaxDynamicSharedMemorySize, SMB);

    fused_kernel<<<GROUPS, CT, SMB>>>(
        r, src0, src1, b00, b01, b10, b11,
        w1, b1, g1, be1, w2, b2, g2, be2,
        w300, b300, w301, b301, w310, b310, w311, b311,
        (float4*)d_out);
}